// round 15
// baseline (speedup 1.0000x reference)
#include <cuda_runtime.h>
#include <cstdint>

#define BB 8
#define NN 256
#define HH 128
#define EPSF 1e-20f
#define NG 256            // 8-tile groups

// Scratch (allocation-free rule: __device__ globals)
__device__ float g_Ux[BB * NN * HH];
__device__ float g_Vx[BB * NN * HH];
__device__ float4 g_p0[NG][4][8][32];   // gate partials  [group][quarter][tile][lane]
__device__ float4 g_p1[NG][4][8][32];   // value partials
__device__ unsigned int g_cnt[NG];      // monotonic tickets (4 per group per replay)

__device__ __forceinline__ float dot4(float4 a, float4 b, float c) {
    return fmaf(a.x, b.x, fmaf(a.y, b.y, fmaf(a.z, b.z, fmaf(a.w, b.w, c))));
}

// ---------------------------------------------------------------------------
// Kernel 1: R10-proven coalesced smem-staged linear (unchanged).
// ---------------------------------------------------------------------------
__global__ __launch_bounds__(256) void linear_kernel(
    const float* __restrict__ x, const float* __restrict__ mask,
    const float* __restrict__ Uw, const float* __restrict__ Ub,
    const float* __restrict__ Vw, const float* __restrict__ Vb)
{
    __shared__ float  ws[32 * 132];
    __shared__ float4 xs[32 * 32];

    const int t  = threadIdx.x;
    const int r0 = blockIdx.x * 32;
    const bool isU = (blockIdx.y < 4);
    const int o0 = (blockIdx.y & 3) * 32;

    const float4* Wg = reinterpret_cast<const float4*>(isU ? Uw : Vw) + (size_t)o0 * 32;
    const float4* Xg = reinterpret_cast<const float4*>(x) + (size_t)r0 * 32;

#pragma unroll
    for (int i = t; i < 1024; i += 256) {
        const int row = i >> 5, c = i & 31;
        reinterpret_cast<float4*>(ws + row * 132)[c] = Wg[i];
        xs[i] = Xg[i];
    }
    __syncthreads();

    const int o_l = t & 31;
    const int wr  = t >> 5;
    const float4* wrow = reinterpret_cast<const float4*>(ws + o_l * 132);
    const float4* xrow = xs + (wr * 4) * 32;

    float a0 = 0.f, a1 = 0.f, a2 = 0.f, a3 = 0.f;
#pragma unroll 8
    for (int k4 = 0; k4 < 32; k4++) {
        const float4 w = wrow[k4];
        a0 = dot4(xrow[k4],      w, a0);
        a1 = dot4(xrow[32 + k4], w, a1);
        a2 = dot4(xrow[64 + k4], w, a2);
        a3 = dot4(xrow[96 + k4], w, a3);
    }

    const int o = o0 + o_l;
    const float bias = isU ? Ub[o] : Vb[o];
    float* dst = isU ? g_Ux : g_Vx;
    const int r = r0 + wr * 4;
    dst[(size_t)(r + 0) * HH + o] = mask[r + 0] * (a0 + bias);
    dst[(size_t)(r + 1) * HH + o] = mask[r + 1] * (a1 + bias);
    dst[(size_t)(r + 2) * HH + o] = mask[r + 2] * (a2 + bias);
    dst[(size_t)(r + 3) * HH + o] = mask[r + 3] * (a3 + bias);
}

// ---------------------------------------------------------------------------
// Kernel 2 (G=8 v-reuse): block = (group of 8 tiles) x (j-quarter, 64 rows).
// grid 1024. Vx slab (32KB) staged to smem ONCE, reused by FOUR sequential
// 2-tile register passes (16 acc regs/pass -> no spill). Vx L2 traffic
// 67MB -> 33MB; total LTS ~343 -> ~310MB (theory: LTS service cap ~7TB/s is
// the binding constraint R6-R14). Partials -> scratch; 4-arrival monotonic
// ticket (R14-proven); 4th block combines + epilogue.
// smem = 32KB vsh + 16KB sh = 48KB exactly -> 4 blocks/SM.
// ---------------------------------------------------------------------------
__global__ __launch_bounds__(256, 4) void edge_kernel(
    const float* __restrict__ eg, const float* __restrict__ mask,
    float* __restrict__ out)
{
    const int t    = threadIdx.x;
    const int lane = t & 31;
    const int w    = t >> 5;            // 0..7
    const int bx   = blockIdx.x;
    const int g    = bx >> 2;           // group 0..255
    const int q    = bx & 3;            // j-quarter
    const int bi0  = g * 8;
    const int b    = bi0 >> 8;          // 8 | 256 -> same b for all 8 tiles
    const int j0   = q * 64;

    __shared__ float4 vsh[2048];        // 64 rows x 32 float4 = 32KB
    __shared__ float4 sh[2][2][8][32];  // [sum][tileInPass][warp][lane] = 16KB

    // stage v slab (coalesced; Vx is L2-hot from linear_kernel)
    const float4* vg = reinterpret_cast<const float4*>(g_Vx)
                       + ((size_t)b * NN + j0) * 32;
#pragma unroll
    for (int i = t; i < 2048; i += 256) vsh[i] = vg[i];

    // per-warp mask slice: 8 rows, FIXED across all passes -> registers
    const float4* mg = reinterpret_cast<const float4*>(mask + (size_t)b * NN + j0 + w * 8);
    const float4 mja = mg[0], mjb = mg[1];
    const float mjs[8] = {mja.x, mja.y, mja.z, mja.w, mjb.x, mjb.y, mjb.z, mjb.w};
    __syncthreads();

    const size_t TS = (size_t)NN * 32;  // tile stride in float4

#pragma unroll 1
    for (int pass = 0; pass < 4; pass++) {
        const int biA = bi0 + pass * 2;
        const float4* epA = reinterpret_cast<const float4*>(eg)
                            + ((size_t)biA * NN + j0 + w * 8) * 32 + lane;
        const float4* epB = epA + TS;
        const float4* vp  = vsh + (w * 8) * 32 + lane;

        float4 sA0 = {0,0,0,0}, sA1 = {0,0,0,0};
        float4 sB0 = {0,0,0,0}, sB1 = {0,0,0,0};

#pragma unroll
        for (int jj = 0; jj < 8; jj++) {
            const float4 e0 = __ldcs(epA); epA += 32;
            const float4 e1 = __ldcs(epB); epB += 32;
            const float4 v  = vp[jj * 32];          // conflict-free LDS.128
            const float mj  = mjs[jj];
            float4 vm;
            vm.x = mj * v.x; vm.y = mj * v.y; vm.z = mj * v.z; vm.w = mj * v.w;

            sA0.x = fmaf(e0.x, mj, sA0.x); sA1.x = fmaf(e0.x, vm.x, sA1.x);
            sA0.y = fmaf(e0.y, mj, sA0.y); sA1.y = fmaf(e0.y, vm.y, sA1.y);
            sA0.z = fmaf(e0.z, mj, sA0.z); sA1.z = fmaf(e0.z, vm.z, sA1.z);
            sA0.w = fmaf(e0.w, mj, sA0.w); sA1.w = fmaf(e0.w, vm.w, sA1.w);

            sB0.x = fmaf(e1.x, mj, sB0.x); sB1.x = fmaf(e1.x, vm.x, sB1.x);
            sB0.y = fmaf(e1.y, mj, sB0.y); sB1.y = fmaf(e1.y, vm.y, sB1.y);
            sB0.z = fmaf(e1.z, mj, sB0.z); sB1.z = fmaf(e1.z, vm.z, sB1.z);
            sB0.w = fmaf(e1.w, mj, sB0.w); sB1.w = fmaf(e1.w, vm.w, sB1.w);
        }

        sh[0][0][w][lane] = sA0;  sh[1][0][w][lane] = sA1;
        sh[0][1][w][lane] = sB0;  sh[1][1][w][lane] = sB1;
        __syncthreads();

        if (t < 64) {
            const int tl = t >> 5, l = t & 31;
            float4 a0 = sh[0][tl][0][l];
            float4 a1 = sh[1][tl][0][l];
#pragma unroll
            for (int k = 1; k < 8; k++) {
                const float4 c0 = sh[0][tl][k][l];
                const float4 c1 = sh[1][tl][k][l];
                a0.x += c0.x; a0.y += c0.y; a0.z += c0.z; a0.w += c0.w;
                a1.x += c1.x; a1.y += c1.y; a1.z += c1.z; a1.w += c1.w;
            }
            g_p0[g][q][pass * 2 + tl][l] = a0;
            g_p1[g][q][pass * 2 + tl][l] = a1;
        }
        __syncthreads();                // sh reused next pass
    }

    // -------- 4-arrival monotonic ticket; 4th block combines --------
    __threadfence();
    __syncthreads();
    unsigned int* flag = reinterpret_cast<unsigned int*>(&sh[0][0][0][0]);
    if (t == 0) *flag = ((atomicAdd(&g_cnt[g], 1u) & 3u) == 3u) ? 1u : 0u;
    __syncthreads();

    if (*flag) {
        const int tile = t >> 5;        // 0..7 -> exactly 256 threads
        const int l    = t & 31;
        float4 a0 = {0,0,0,0}, a1 = {0,0,0,0};
#pragma unroll
        for (int qq = 0; qq < 4; qq++) {
            const float4 c0 = __ldcg(&g_p0[g][qq][tile][l]);
            const float4 c1 = __ldcg(&g_p1[g][qq][tile][l]);
            a0.x += c0.x; a0.y += c0.y; a0.z += c0.z; a0.w += c0.w;
            a1.x += c1.x; a1.y += c1.y; a1.z += c1.z; a1.w += c1.w;
        }
        const int bi = bi0 + tile;
        const float mi = mask[bi];      // mask[b*NN + (bi&255)] == mask[bi]
        const float4 ux = reinterpret_cast<const float4*>(g_Ux)[(size_t)bi * 32 + l];
        float4 o;
        o.x = ux.x + (mi * a1.x) / (EPSF + mi * a0.x);
        o.y = ux.y + (mi * a1.y) / (EPSF + mi * a0.y);
        o.z = ux.z + (mi * a1.z) / (EPSF + mi * a0.z);
        o.w = ux.w + (mi * a1.w) / (EPSF + mi * a0.w);
        reinterpret_cast<float4*>(out)[(size_t)bi * 32 + l] = o;
    }
}

extern "C" void kernel_launch(void* const* d_in, const int* in_sizes, int n_in,
                              void* d_out, int out_size)
{
    const float* x   = (const float*)d_in[0];
    const float* eg  = (const float*)d_in[1];
    const float* msk = (const float*)d_in[2];
    const float* Uw  = (const float*)d_in[3];
    const float* Ub  = (const float*)d_in[4];
    const float* Vw  = (const float*)d_in[5];
    const float* Vb  = (const float*)d_in[6];
    float* out = (float*)d_out;

    dim3 lgrid(64, 8);
    linear_kernel<<<lgrid, 256>>>(x, msk, Uw, Ub, Vw, Vb);
    edge_kernel<<<NG * 4, 256>>>(eg, msk, out);
}

// round 17
// speedup vs baseline: 1.1336x; 1.1336x over previous
#include <cuda_runtime.h>
#include <cstdint>

#define BB 8
#define NN 256
#define HH 128
#define EPSF 1e-20f

// Scratch (allocation-free rule: __device__ globals)
__device__ float g_Ux[BB * NN * HH];
__device__ float g_Vx[BB * NN * HH];

__device__ __forceinline__ float dot4(float4 a, float4 b, float c) {
    return fmaf(a.x, b.x, fmaf(a.y, b.y, fmaf(a.z, b.z, fmaf(a.w, b.w, c))));
}

// ---------------------------------------------------------------------------
// Kernel 1 (v2): 64-o x 32-row blocks, grid (64,4) = 256 blocks x 256 thr.
// Lane l owns o-pair {o0+l, o0+32+l}: ws rows l and l+32 both hit bank l
// under the 132-float row stride -> conflict-free LDS.128. Thread = 2o x 4
// rows -> 6 LDS per 8 dot4 (R10: 5 per 4) and each weight tile staged ONCE
// (R10 staged every 32-o tile twice). Halves linear's LDS-crossbar cost.
// ---------------------------------------------------------------------------
__global__ __launch_bounds__(256) void linear_kernel(
    const float* __restrict__ x, const float* __restrict__ mask,
    const float* __restrict__ Uw, const float* __restrict__ Ub,
    const float* __restrict__ Vw, const float* __restrict__ Vb)
{
    __shared__ float  ws[64 * 132];      // 64 weight rows, stride 33 float4
    __shared__ float4 xs[32 * 32];       // 32 x-rows (broadcast reads)

    const int t  = threadIdx.x;
    const int r0 = blockIdx.x * 32;
    const bool isU = (blockIdx.y < 2);
    const int o0 = (blockIdx.y & 1) * 64;

    const float4* Wg = reinterpret_cast<const float4*>(isU ? Uw : Vw) + (size_t)o0 * 32;
    const float4* Xg = reinterpret_cast<const float4*>(x) + (size_t)r0 * 32;

    // stage weights: 64 rows x 32 float4 = 2048 (coalesced, 8 iters)
#pragma unroll
    for (int i = t; i < 2048; i += 256) {
        const int row = i >> 5, c = i & 31;
        reinterpret_cast<float4*>(ws + row * 132)[c] = Wg[i];
    }
    // stage x: 32 rows x 32 float4 = 1024 (4 iters)
#pragma unroll
    for (int i = t; i < 1024; i += 256) xs[i] = Xg[i];
    __syncthreads();

    const int l  = t & 31;
    const int wr = t >> 5;
    const float4* wrow0 = reinterpret_cast<const float4*>(ws + l * 132);
    const float4* wrow1 = reinterpret_cast<const float4*>(ws + (l + 32) * 132);
    const float4* xrow  = xs + (wr * 4) * 32;

    float a00 = 0.f, a01 = 0.f, a02 = 0.f, a03 = 0.f;   // o = o0+l
    float a10 = 0.f, a11 = 0.f, a12 = 0.f, a13 = 0.f;   // o = o0+32+l
#pragma unroll 4
    for (int k4 = 0; k4 < 32; k4++) {
        const float4 w0 = wrow0[k4];     // conflict-free (bank l)
        const float4 w1 = wrow1[k4];     // conflict-free (bank l)
        const float4 x0 = xrow[k4];      // broadcast
        const float4 x1 = xrow[32 + k4];
        const float4 x2 = xrow[64 + k4];
        const float4 x3 = xrow[96 + k4];
        a00 = dot4(x0, w0, a00);  a10 = dot4(x0, w1, a10);
        a01 = dot4(x1, w0, a01);  a11 = dot4(x1, w1, a11);
        a02 = dot4(x2, w0, a02);  a12 = dot4(x2, w1, a12);
        a03 = dot4(x3, w0, a03);  a13 = dot4(x3, w1, a13);
    }

    const int oA = o0 + l, oB = o0 + 32 + l;
    const float bA = isU ? Ub[oA] : Vb[oA];
    const float bB = isU ? Ub[oB] : Vb[oB];
    float* dst = isU ? g_Ux : g_Vx;
    const int r = r0 + wr * 4;
    const float m0 = mask[r], m1 = mask[r + 1], m2 = mask[r + 2], m3 = mask[r + 3];
    // lanes -> 32 consecutive o at fixed row: 128B coalesced stores
    dst[(size_t)(r + 0) * HH + oA] = m0 * (a00 + bA);
    dst[(size_t)(r + 1) * HH + oA] = m1 * (a01 + bA);
    dst[(size_t)(r + 2) * HH + oA] = m2 * (a02 + bA);
    dst[(size_t)(r + 3) * HH + oA] = m3 * (a03 + bA);
    dst[(size_t)(r + 0) * HH + oB] = m0 * (a10 + bB);
    dst[(size_t)(r + 1) * HH + oB] = m1 * (a11 + bB);
    dst[(size_t)(r + 2) * HH + oB] = m2 * (a12 + bB);
    dst[(size_t)(r + 3) * HH + oB] = m3 * (a13 + bB);
}

// ---------------------------------------------------------------------------
// Kernel 2: R11 edge kernel, byte-identical (proven 47.9us @ 72.3% DRAM).
// G=4 v-reuse, register-resident, grid 512 x 256, single wave.
// ---------------------------------------------------------------------------
__global__ __launch_bounds__(256, 4) void edge_kernel(
    const float* __restrict__ eg, const float* __restrict__ mask,
    float* __restrict__ out)
{
    const int t    = threadIdx.x;
    const int lane = t & 31;
    const int w    = t >> 5;            // 0..7 : j-chunk
    const int bi0  = blockIdx.x * 4;
    const int b    = bi0 >> 8;          // 4 | 256 -> same b for all 4 tiles

    __shared__ float  msk[NN];
    __shared__ float4 sh[2][4][8][32];  // [sum][tile][warp][lane] = 32KB

    msk[t] = mask[b * NN + t];
    __syncthreads();

    const int j0 = w * 32;
    const float4* ep = reinterpret_cast<const float4*>(eg)
                       + ((size_t)bi0 * NN + j0) * 32 + lane;
    const float4* vp = reinterpret_cast<const float4*>(g_Vx)
                       + ((size_t)b * NN + j0) * 32 + lane;
    const float* mp = &msk[j0];

    float4 s00 = {0,0,0,0}, s01 = {0,0,0,0}, s02 = {0,0,0,0}, s03 = {0,0,0,0};
    float4 s10 = {0,0,0,0}, s11 = {0,0,0,0}, s12 = {0,0,0,0}, s13 = {0,0,0,0};

    const size_t TS = (size_t)NN * 32;  // tile stride in float4

#pragma unroll 2
    for (int jj = 0; jj < 32; jj++) {
        const float4 e0 = __ldcs(ep);
        const float4 e1 = __ldcs(ep + TS);
        const float4 e2 = __ldcs(ep + 2 * TS);
        const float4 e3 = __ldcs(ep + 3 * TS);
        ep += 32;
        const float4 v = __ldg(vp); vp += 32;
        const float mj = mp[jj];
        float4 vm;
        vm.x = mj * v.x; vm.y = mj * v.y; vm.z = mj * v.z; vm.w = mj * v.w;

        s00.x = fmaf(e0.x, mj, s00.x); s10.x = fmaf(e0.x, vm.x, s10.x);
        s00.y = fmaf(e0.y, mj, s00.y); s10.y = fmaf(e0.y, vm.y, s10.y);
        s00.z = fmaf(e0.z, mj, s00.z); s10.z = fmaf(e0.z, vm.z, s10.z);
        s00.w = fmaf(e0.w, mj, s00.w); s10.w = fmaf(e0.w, vm.w, s10.w);

        s01.x = fmaf(e1.x, mj, s01.x); s11.x = fmaf(e1.x, vm.x, s11.x);
        s01.y = fmaf(e1.y, mj, s01.y); s11.y = fmaf(e1.y, vm.y, s11.y);
        s01.z = fmaf(e1.z, mj, s01.z); s11.z = fmaf(e1.z, vm.z, s11.z);
        s01.w = fmaf(e1.w, mj, s01.w); s11.w = fmaf(e1.w, vm.w, s11.w);

        s02.x = fmaf(e2.x, mj, s02.x); s12.x = fmaf(e2.x, vm.x, s12.x);
        s02.y = fmaf(e2.y, mj, s02.y); s12.y = fmaf(e2.y, vm.y, s12.y);
        s02.z = fmaf(e2.z, mj, s02.z); s12.z = fmaf(e2.z, vm.z, s12.z);
        s02.w = fmaf(e2.w, mj, s02.w); s12.w = fmaf(e2.w, vm.w, s12.w);

        s03.x = fmaf(e3.x, mj, s03.x); s13.x = fmaf(e3.x, vm.x, s13.x);
        s03.y = fmaf(e3.y, mj, s03.y); s13.y = fmaf(e3.y, vm.y, s13.y);
        s03.z = fmaf(e3.z, mj, s03.z); s13.z = fmaf(e3.z, vm.z, s13.z);
        s03.w = fmaf(e3.w, mj, s03.w); s13.w = fmaf(e3.w, vm.w, s13.w);
    }

    sh[0][0][w][lane] = s00;  sh[1][0][w][lane] = s10;
    sh[0][1][w][lane] = s01;  sh[1][1][w][lane] = s11;
    sh[0][2][w][lane] = s02;  sh[1][2][w][lane] = s12;
    sh[0][3][w][lane] = s03;  sh[1][3][w][lane] = s13;
    __syncthreads();

    if (t < 128) {
        const int tile = t >> 5;        // 0..3
        const int l    = t & 31;
        float4 a0 = sh[0][tile][0][l];
        float4 a1 = sh[1][tile][0][l];
#pragma unroll
        for (int k = 1; k < 8; k++) {
            const float4 b0 = sh[0][tile][k][l];
            const float4 b1 = sh[1][tile][k][l];
            a0.x += b0.x; a0.y += b0.y; a0.z += b0.z; a0.w += b0.w;
            a1.x += b1.x; a1.y += b1.y; a1.z += b1.z; a1.w += b1.w;
        }
        const int bi = bi0 + tile;
        const float mi = msk[bi & 255];
        const float4 ux = reinterpret_cast<const float4*>(g_Ux)[(size_t)bi * 32 + l];
        float4 o;
        o.x = ux.x + (mi * a1.x) / (EPSF + mi * a0.x);
        o.y = ux.y + (mi * a1.y) / (EPSF + mi * a0.y);
        o.z = ux.z + (mi * a1.z) / (EPSF + mi * a0.z);
        o.w = ux.w + (mi * a1.w) / (EPSF + mi * a0.w);
        reinterpret_cast<float4*>(out)[(size_t)bi * 32 + l] = o;
    }
}

extern "C" void kernel_launch(void* const* d_in, const int* in_sizes, int n_in,
                              void* d_out, int out_size)
{
    const float* x   = (const float*)d_in[0];
    const float* eg  = (const float*)d_in[1];
    const float* msk = (const float*)d_in[2];
    const float* Uw  = (const float*)d_in[3];
    const float* Ub  = (const float*)d_in[4];
    const float* Vw  = (const float*)d_in[5];
    const float* Vb  = (const float*)d_in[6];
    float* out = (float*)d_out;

    dim3 lgrid(64, 4);
    linear_kernel<<<lgrid, 256>>>(x, msk, Uw, Ub, Vw, Vb);
    edge_kernel<<<(BB * NN) / 4, 256>>>(eg, msk, out);
}